// round 5
// baseline (speedup 1.0000x reference)
#include <cuda_runtime.h>
#include <cuda_bf16.h>
#include <cstdint>

// ============================================================================
// Problem: B=8, N=8192, S=8, D_IN=64, D_OUT=64;  nodes = 65536
//   PQR = x @ [W1a|W1b|W1c]  (65536 x 384), b1 folded into P   [GEMM1]
//   G   = mean_s gelu(P + Q[j_s] + R[k_s])   (65536 x 128)     [mid]
//   out = G @ W2 + b2                        (65536 x 64)      [GEMM2]
// Tensor path: legacy mma.sync m16n8k16 bf16 (compute_103-legal), split-bf16
// 3-term (Ah*Bh + Ah*Bl + Al*Bh) for fp32-grade accuracy.
// ============================================================================

static constexpr int NODES = 65536;

// Scratch (device globals: allocation-guard-safe; zero-initialized)
__device__ float g_PQR[(size_t)NODES * 384];                    // 96 MB fp32
__device__ __align__(16) unsigned char g_Ghi[(size_t)NODES * 256];  // G hi plane, 256B/row
__device__ __align__(16) unsigned char g_Glo[(size_t)NODES * 256];  // G lo plane

// Pre-converted weight tile byte images (same pitch as the GEMM smem tiles)
// W1: 384 n-rows x 64 k, bf16, pitch 144B.  W2: 64 n-rows x 128 k, pitch 272B.
__device__ __align__(16) unsigned char g_W1hi[384 * 144];
__device__ __align__(16) unsigned char g_W1lo[384 * 144];
__device__ __align__(16) unsigned char g_W2hi[64 * 272];
__device__ __align__(16) unsigned char g_W2lo[64 * 272];

// ---------------------------------------------------------------------------
// Helpers
// ---------------------------------------------------------------------------
__device__ __forceinline__ void split_bf16(float v, __nv_bfloat16& h, __nv_bfloat16& l) {
    h = __float2bfloat16(v);
    l = __float2bfloat16(v - __bfloat162float(h));
}

__device__ __forceinline__ uint32_t pack_hi(float a, float b) {
    __nv_bfloat162 t = __halves2bfloat162(__float2bfloat16(a), __float2bfloat16(b));
    return *reinterpret_cast<uint32_t*>(&t);
}

// mma.sync m16n8k16 row.col f32.bf16.bf16.f32  (sm_80+ baseline PTX)
__device__ __forceinline__ void mma16816(float* d, const uint32_t* a, const uint32_t* b) {
    asm("mma.sync.aligned.m16n8k16.row.col.f32.bf16.bf16.f32 "
        "{%0,%1,%2,%3}, {%4,%5,%6,%7}, {%8,%9}, {%0,%1,%2,%3};"
        : "+f"(d[0]), "+f"(d[1]), "+f"(d[2]), "+f"(d[3])
        : "r"(a[0]), "r"(a[1]), "r"(a[2]), "r"(a[3]), "r"(b[0]), "r"(b[1]));
}

// ---------------------------------------------------------------------------
// Kernel 0: convert W1/W2 -> split-bf16 padded-pitch byte images (one-time).
//   W1 image: B[n][k] = W1[(n/128)*64 + k][n%128], n<384, k<64, pitch 144B.
//   W2 image: B[n][k] = W2[k][n],                 n<64, k<128, pitch 272B.
// ---------------------------------------------------------------------------
__global__ __launch_bounds__(256)
void prep_kernel(const float* __restrict__ W1, const float* __restrict__ W2) {
    int idx = blockIdx.x * 256 + threadIdx.x;      // 0 .. 16383
    if (idx < 12288) {
        int n = idx >> 5, kp = idx & 31;           // 384 rows x 32 k-pairs
        int t = n >> 7, c = n & 127, k = kp * 2;
        float w0 = W1[(size_t)(t * 64 + k) * 128 + c];
        float w1 = W1[(size_t)(t * 64 + k + 1) * 128 + c];
        __nv_bfloat16 h0, l0, h1, l1;
        split_bf16(w0, h0, l0);
        split_bf16(w1, h1, l1);
        __nv_bfloat162 hh = __halves2bfloat162(h0, h1), ll = __halves2bfloat162(l0, l1);
        *reinterpret_cast<uint32_t*>(g_W1hi + n * 144 + kp * 4) = *reinterpret_cast<uint32_t*>(&hh);
        *reinterpret_cast<uint32_t*>(g_W1lo + n * 144 + kp * 4) = *reinterpret_cast<uint32_t*>(&ll);
    } else if (idx < 16384) {
        int i = idx - 12288;                       // 64 rows x 64 k-pairs
        int n = i >> 6, kp = i & 63, k = kp * 2;
        float w0 = W2[(size_t)k * 64 + n];
        float w1 = W2[(size_t)(k + 1) * 64 + n];
        __nv_bfloat16 h0, l0, h1, l1;
        split_bf16(w0, h0, l0);
        split_bf16(w1, h1, l1);
        __nv_bfloat162 hh = __halves2bfloat162(h0, h1), ll = __halves2bfloat162(l0, l1);
        *reinterpret_cast<uint32_t*>(g_W2hi + n * 272 + kp * 4) = *reinterpret_cast<uint32_t*>(&hh);
        *reinterpret_cast<uint32_t*>(g_W2lo + n * 272 + kp * 4) = *reinterpret_cast<uint32_t*>(&ll);
    }
}

// ---------------------------------------------------------------------------
// Kernel 1: PQR = x @ W1concat.  CTA tile M=128 x N=128 (grid.y = 3 N-chunks).
//   256 threads, 8 warps (2M x 4N), warp tile m64n32, K=64 (4 k-steps).
//   smem: A hi/lo 128x64 bf16 pitch 144B; B hi/lo 128x64 pitch 144B. 72KB.
// ---------------------------------------------------------------------------
static constexpr int SMEM1_BYTES = 4 * 128 * 144;   // 73728

__global__ __launch_bounds__(256, 2)
void gemm1_kernel(const float* __restrict__ x, const float* __restrict__ b1) {
    extern __shared__ char sm[];
    const int tid = threadIdx.x, wid = tid >> 5, lane = tid & 31;
    const int gr = lane >> 2, tg = lane & 3;
    const int warpM = wid >> 2, warpN = wid & 3;
    const int m0 = blockIdx.x * 128, pass = blockIdx.y;

    char* Ah = sm;
    char* Al = sm + 18432;
    char* Bh = sm + 36864;
    char* Bl = sm + 55296;

    // B tiles: verbatim copy of the pass's 128-row slice of the weight images
    {
        const uint4* sh = reinterpret_cast<const uint4*>(g_W1hi + pass * 128 * 144);
        const uint4* sl = reinterpret_cast<const uint4*>(g_W1lo + pass * 128 * 144);
        uint4* dh = reinterpret_cast<uint4*>(Bh);
        uint4* dl = reinterpret_cast<uint4*>(Bl);
        for (int i = tid; i < 1152; i += 256) { dh[i] = sh[i]; dl[i] = sl[i]; }
    }
    // A tile: x (128 rows x 64 fp32) -> split bf16 hi/lo, pitch 144B
    for (int i = tid; i < 4096; i += 256) {
        int r = i >> 5, kp = i & 31;
        float2 v = *reinterpret_cast<const float2*>(x + (size_t)(m0 + r) * 64 + kp * 2);
        __nv_bfloat16 h0, l0, h1, l1;
        split_bf16(v.x, h0, l0);
        split_bf16(v.y, h1, l1);
        __nv_bfloat162 hh = __halves2bfloat162(h0, h1), ll = __halves2bfloat162(l0, l1);
        *reinterpret_cast<uint32_t*>(Ah + r * 144 + kp * 4) = *reinterpret_cast<uint32_t*>(&hh);
        *reinterpret_cast<uint32_t*>(Al + r * 144 + kp * 4) = *reinterpret_cast<uint32_t*>(&ll);
    }
    __syncthreads();

    float acc[4][4][4];
#pragma unroll
    for (int mt = 0; mt < 4; mt++)
#pragma unroll
        for (int nt = 0; nt < 4; nt++)
#pragma unroll
            for (int e = 0; e < 4; e++) acc[mt][nt][e] = 0.f;

#pragma unroll
    for (int ks = 0; ks < 4; ks++) {
        const int kb = ks * 32 + tg * 4;
        uint32_t ah[4][4], al[4][4], bh[4][2], bl[4][2];
#pragma unroll
        for (int mt = 0; mt < 4; mt++) {
            const char* p = Ah + (warpM * 64 + mt * 16 + gr) * 144 + kb;
            const char* q = Al + (warpM * 64 + mt * 16 + gr) * 144 + kb;
            ah[mt][0] = *reinterpret_cast<const uint32_t*>(p);
            ah[mt][1] = *reinterpret_cast<const uint32_t*>(p + 8 * 144);
            ah[mt][2] = *reinterpret_cast<const uint32_t*>(p + 16);
            ah[mt][3] = *reinterpret_cast<const uint32_t*>(p + 8 * 144 + 16);
            al[mt][0] = *reinterpret_cast<const uint32_t*>(q);
            al[mt][1] = *reinterpret_cast<const uint32_t*>(q + 8 * 144);
            al[mt][2] = *reinterpret_cast<const uint32_t*>(q + 16);
            al[mt][3] = *reinterpret_cast<const uint32_t*>(q + 8 * 144 + 16);
        }
#pragma unroll
        for (int nt = 0; nt < 4; nt++) {
            const char* p = Bh + (warpN * 32 + nt * 8 + gr) * 144 + kb;
            const char* q = Bl + (warpN * 32 + nt * 8 + gr) * 144 + kb;
            bh[nt][0] = *reinterpret_cast<const uint32_t*>(p);
            bh[nt][1] = *reinterpret_cast<const uint32_t*>(p + 16);
            bl[nt][0] = *reinterpret_cast<const uint32_t*>(q);
            bl[nt][1] = *reinterpret_cast<const uint32_t*>(q + 16);
        }
#pragma unroll
        for (int mt = 0; mt < 4; mt++)
#pragma unroll
            for (int nt = 0; nt < 4; nt++) {
                mma16816(acc[mt][nt], ah[mt], bh[nt]);
                mma16816(acc[mt][nt], ah[mt], bl[nt]);
                mma16816(acc[mt][nt], al[mt], bh[nt]);
            }
    }

    // Epilogue: direct float2 stores (+b1 on pass 0)
#pragma unroll
    for (int mt = 0; mt < 4; mt++) {
        int row = m0 + warpM * 64 + mt * 16 + gr;
#pragma unroll
        for (int nt = 0; nt < 4; nt++) {
            int colL = warpN * 32 + nt * 8 + tg * 2;
            float2 v0 = make_float2(acc[mt][nt][0], acc[mt][nt][1]);
            float2 v1 = make_float2(acc[mt][nt][2], acc[mt][nt][3]);
            if (pass == 0) {
                float2 bb = *reinterpret_cast<const float2*>(b1 + colL);
                v0.x += bb.x; v0.y += bb.y; v1.x += bb.x; v1.y += bb.y;
            }
            int col = pass * 128 + colL;
            *reinterpret_cast<float2*>(g_PQR + (size_t)row * 384 + col) = v0;
            *reinterpret_cast<float2*>(g_PQR + (size_t)(row + 8) * 384 + col) = v1;
        }
    }
}

// ---------------------------------------------------------------------------
// Kernel 2: G = mean_s gelu(P + Q[j] + R[k]); emits split-bf16 hi/lo planes.
//   One warp per node; lane owns 4 cols. Batched gathers (MLP~8).
// ---------------------------------------------------------------------------
__device__ __forceinline__ float gelu_f(float v) {
    return 0.5f * v * (1.0f + erff(v * 0.70710678118654752f));
}

__global__ __launch_bounds__(256)
void mid_kernel(const int* __restrict__ jidx, const int* __restrict__ kidx) {
    int gw = (int)((blockIdx.x * 256u + threadIdx.x) >> 5);    // node 0..65535
    int lane = threadIdx.x & 31;
    int base = (gw >> 13) << 13;                               // batch row base
    const float4* P4 = reinterpret_cast<const float4*>(g_PQR); // row stride 96 f4

    float4 p = P4[(size_t)gw * 96 + lane];
    float ax = 0.f, ay = 0.f, az = 0.f, aw = 0.f;

#pragma unroll
    for (int half = 0; half < 2; half++) {
        int s0 = half * 4;
        int j[4], k[4];
#pragma unroll
        for (int u = 0; u < 4; u++) {
            j[u] = __ldg(jidx + gw * 8 + s0 + u);
            k[u] = __ldg(kidx + gw * 8 + s0 + u);
        }
        float4 q[4], r[4];
#pragma unroll
        for (int u = 0; u < 4; u++) {
            q[u] = P4[(size_t)(base + j[u]) * 96 + 32 + lane];
            r[u] = P4[(size_t)(base + k[u]) * 96 + 64 + lane];
        }
#pragma unroll
        for (int u = 0; u < 4; u++) {
            ax += gelu_f(p.x + q[u].x + r[u].x);
            ay += gelu_f(p.y + q[u].y + r[u].y);
            az += gelu_f(p.z + q[u].z + r[u].z);
            aw += gelu_f(p.w + q[u].w + r[u].w);
        }
    }
    float g0 = ax * 0.125f, g1 = ay * 0.125f, g2 = az * 0.125f, g3 = aw * 0.125f;
    __nv_bfloat16 h0, l0, h1, l1, h2, l2, h3, l3;
    split_bf16(g0, h0, l0);
    split_bf16(g1, h1, l1);
    split_bf16(g2, h2, l2);
    split_bf16(g3, h3, l3);
    __nv_bfloat162 hA = __halves2bfloat162(h0, h1), hB = __halves2bfloat162(h2, h3);
    __nv_bfloat162 lA = __halves2bfloat162(l0, l1), lB = __halves2bfloat162(l2, l3);
    uint2 hv = make_uint2(*reinterpret_cast<uint32_t*>(&hA), *reinterpret_cast<uint32_t*>(&hB));
    uint2 lv = make_uint2(*reinterpret_cast<uint32_t*>(&lA), *reinterpret_cast<uint32_t*>(&lB));
    *reinterpret_cast<uint2*>(g_Ghi + (size_t)gw * 256 + lane * 8) = hv;
    *reinterpret_cast<uint2*>(g_Glo + (size_t)gw * 256 + lane * 8) = lv;
}

// ---------------------------------------------------------------------------
// Kernel 3: out = G @ W2 + b2.  CTA tile M=128 x N=64, 128 threads (4 warps,
//   2M x 2N, warp tile m64n32), K=128 (8 k-steps), smem pitch 272B. 102KB.
// ---------------------------------------------------------------------------
static constexpr int SMEM2_BYTES = 2 * 128 * 272 + 2 * 64 * 272;  // 104448

__global__ __launch_bounds__(128, 1)
void gemm2_kernel(const float* __restrict__ b2, float* __restrict__ out) {
    extern __shared__ char sm[];
    const int tid = threadIdx.x, wid = tid >> 5, lane = tid & 31;
    const int gr = lane >> 2, tg = lane & 3;
    const int warpM = wid >> 1, warpN = wid & 1;
    const int m0 = blockIdx.x * 128;

    char* Ah = sm;
    char* Al = sm + 34816;
    char* Bh = sm + 69632;
    char* Bl = sm + 87040;

    // B tiles: verbatim copy of pitch-identical weight images (1088 uint4 each)
    {
        const uint4* sh = reinterpret_cast<const uint4*>(g_W2hi);
        const uint4* sl = reinterpret_cast<const uint4*>(g_W2lo);
        uint4* dh = reinterpret_cast<uint4*>(Bh);
        uint4* dl = reinterpret_cast<uint4*>(Bl);
        for (int i = tid; i < 1088; i += 128) { dh[i] = sh[i]; dl[i] = sl[i]; }
    }
    // A tiles: copy G hi/lo rows (16 uint4 of data per 17-uint4 pitched row)
    {
        const uint4* sh = reinterpret_cast<const uint4*>(g_Ghi) + (size_t)m0 * 16;
        const uint4* sl = reinterpret_cast<const uint4*>(g_Glo) + (size_t)m0 * 16;
        uint4* dh = reinterpret_cast<uint4*>(Ah);
        uint4* dl = reinterpret_cast<uint4*>(Al);
        for (int i = tid; i < 2048; i += 128) {
            int r = i >> 4, q = i & 15;
            dh[r * 17 + q] = sh[i];
            dl[r * 17 + q] = sl[i];
        }
    }
    __syncthreads();

    float acc[4][4][4];
#pragma unroll
    for (int mt = 0; mt < 4; mt++)
#pragma unroll
        for (int nt = 0; nt < 4; nt++)
#pragma unroll
            for (int e = 0; e < 4; e++) acc[mt][nt][e] = 0.f;

#pragma unroll
    for (int ks = 0; ks < 8; ks++) {
        const int kb = ks * 32 + tg * 4;
        uint32_t ah[4][4], al[4][4], bh[4][2], bl[4][2];
#pragma unroll
        for (int mt = 0; mt < 4; mt++) {
            const char* p = Ah + (warpM * 64 + mt * 16 + gr) * 272 + kb;
            const char* q = Al + (warpM * 64 + mt * 16 + gr) * 272 + kb;
            ah[mt][0] = *reinterpret_cast<const uint32_t*>(p);
            ah[mt][1] = *reinterpret_cast<const uint32_t*>(p + 8 * 272);
            ah[mt][2] = *reinterpret_cast<const uint32_t*>(p + 16);
            ah[mt][3] = *reinterpret_cast<const uint32_t*>(p + 8 * 272 + 16);
            al[mt][0] = *reinterpret_cast<const uint32_t*>(q);
            al[mt][1] = *reinterpret_cast<const uint32_t*>(q + 8 * 272);
            al[mt][2] = *reinterpret_cast<const uint32_t*>(q + 16);
            al[mt][3] = *reinterpret_cast<const uint32_t*>(q + 8 * 272 + 16);
        }
#pragma unroll
        for (int nt = 0; nt < 4; nt++) {
            const char* p = Bh + (warpN * 32 + nt * 8 + gr) * 272 + kb;
            const char* q = Bl + (warpN * 32 + nt * 8 + gr) * 272 + kb;
            bh[nt][0] = *reinterpret_cast<const uint32_t*>(p);
            bh[nt][1] = *reinterpret_cast<const uint32_t*>(p + 16);
            bl[nt][0] = *reinterpret_cast<const uint32_t*>(q);
            bl[nt][1] = *reinterpret_cast<const uint32_t*>(q + 16);
        }
#pragma unroll
        for (int mt = 0; mt < 4; mt++)
#pragma unroll
            for (int nt = 0; nt < 4; nt++) {
                mma16816(acc[mt][nt], ah[mt], bh[nt]);
                mma16816(acc[mt][nt], ah[mt], bl[nt]);
                mma16816(acc[mt][nt], al[mt], bh[nt]);
            }
    }

    // Epilogue: +b2, direct float2 stores
#pragma unroll
    for (int mt = 0; mt < 4; mt++) {
        int row = m0 + warpM * 64 + mt * 16 + gr;
#pragma unroll
        for (int nt = 0; nt < 4; nt++) {
            int col = warpN * 32 + nt * 8 + tg * 2;
            float2 bb = *reinterpret_cast<const float2*>(b2 + col);
            float2 v0 = make_float2(acc[mt][nt][0] + bb.x, acc[mt][nt][1] + bb.y);
            float2 v1 = make_float2(acc[mt][nt][2] + bb.x, acc[mt][nt][3] + bb.y);
            *reinterpret_cast<float2*>(out + (size_t)row * 64 + col) = v0;
            *reinterpret_cast<float2*>(out + (size_t)(row + 8) * 64 + col) = v1;
        }
    }
}

// ---------------------------------------------------------------------------
// Host launcher (graph-capturable: kernel launches only)
// ---------------------------------------------------------------------------
extern "C" void kernel_launch(void* const* d_in, const int* in_sizes, int n_in,
                              void* d_out, int out_size) {
    (void)in_sizes; (void)n_in; (void)out_size;
    const float* x   = (const float*)d_in[0];
    const int*   jid = (const int*)  d_in[1];
    const int*   kid = (const int*)  d_in[2];
    const float* W1  = (const float*)d_in[3];
    const float* b1  = (const float*)d_in[4];
    const float* W2  = (const float*)d_in[5];
    const float* b2  = (const float*)d_in[6];
    float* out = (float*)d_out;

    cudaFuncSetAttribute(gemm1_kernel, cudaFuncAttributeMaxDynamicSharedMemorySize, SMEM1_BYTES);
    cudaFuncSetAttribute(gemm2_kernel, cudaFuncAttributeMaxDynamicSharedMemorySize, SMEM2_BYTES);

    prep_kernel<<<64, 256>>>(W1, W2);
    gemm1_kernel<<<dim3(512, 3), 256, SMEM1_BYTES>>>(x, b1);
    mid_kernel<<<NODES / 8, 256>>>(jid, kid);
    gemm2_kernel<<<512, 128, SMEM2_BYTES>>>(b2, out);
}

// round 10
// speedup vs baseline: 1.0500x; 1.0500x over previous
#include <cuda_runtime.h>
#include <cuda_bf16.h>
#include <cstdint>

// ============================================================================
// Problem: B=8, N=8192, S=8, D_IN=64, D_OUT=64;  nodes = 65536
//   PQR = x @ [W1a|W1b|W1c]  (65536 x 384), b1 folded into P   [GEMM1]
//   G   = mean_s gelu(P + Q[j_s] + R[k_s])   (65536 x 128)     [mid]
//   out = G @ W2 + b2                        (65536 x 64)      [GEMM2]
// Tensor path: legacy mma.sync m16n8k16 bf16, split-bf16 3-term.
// R6: m32n32 warp tiles + small CTA tiles for occupancy; all operand tiles
// pre-converted to pitched byte images so GEMM loads are verbatim copies.
// ============================================================================

static constexpr int NODES = 65536;

// Scratch (device globals: allocation-guard-safe)
__device__ float g_PQR[(size_t)NODES * 384];                        // 96 MB fp32
__device__ __align__(16) unsigned char g_Xhi[(size_t)NODES * 144];  // x hi, pitch 144B
__device__ __align__(16) unsigned char g_Xlo[(size_t)NODES * 144];
__device__ __align__(16) unsigned char g_Ghi[(size_t)NODES * 272];  // G hi, pitch 272B
__device__ __align__(16) unsigned char g_Glo[(size_t)NODES * 272];

// Weight tile byte images (pitch matches GEMM smem tiles)
__device__ __align__(16) unsigned char g_W1hi[384 * 144];
__device__ __align__(16) unsigned char g_W1lo[384 * 144];
__device__ __align__(16) unsigned char g_W2hi[64 * 272];
__device__ __align__(16) unsigned char g_W2lo[64 * 272];

// ---------------------------------------------------------------------------
__device__ __forceinline__ void split_bf16(float v, __nv_bfloat16& h, __nv_bfloat16& l) {
    h = __float2bfloat16(v);
    l = __float2bfloat16(v - __bfloat162float(h));
}

// mma.sync m16n8k16 row.col f32.bf16.bf16.f32  (sm_80+ baseline PTX)
__device__ __forceinline__ void mma16816(float* d, const uint32_t* a, const uint32_t* b) {
    asm("mma.sync.aligned.m16n8k16.row.col.f32.bf16.bf16.f32 "
        "{%0,%1,%2,%3}, {%4,%5,%6,%7}, {%8,%9}, {%0,%1,%2,%3};"
        : "+f"(d[0]), "+f"(d[1]), "+f"(d[2]), "+f"(d[3])
        : "r"(a[0]), "r"(a[1]), "r"(a[2]), "r"(a[3]), "r"(b[0]), "r"(b[1]));
}

// ---------------------------------------------------------------------------
// Kernel 0: one-time conversions to split-bf16 pitched byte images.
//   x:  65536 rows x 64 k  -> g_Xhi/g_Xlo, pitch 144B
//   W1: B[n][k] = W1[(n/128)*64+k][n%128], 384 x 64, pitch 144B
//   W2: B[n][k] = W2[k][n], 64 x 128, pitch 272B
// ---------------------------------------------------------------------------
static constexpr int PREP_X = NODES * 32;          // 2097152 pair-slots
static constexpr int PREP_TOTAL = PREP_X + 16384;

__global__ __launch_bounds__(256)
void prep_kernel(const float* __restrict__ x, const float* __restrict__ W1,
                 const float* __restrict__ W2) {
    int idx = blockIdx.x * 256 + threadIdx.x;
    if (idx < PREP_X) {
        int r = idx >> 5, kp = idx & 31;
        float2 v = *reinterpret_cast<const float2*>(x + (size_t)r * 64 + kp * 2);
        __nv_bfloat16 h0, l0, h1, l1;
        split_bf16(v.x, h0, l0);
        split_bf16(v.y, h1, l1);
        __nv_bfloat162 hh = __halves2bfloat162(h0, h1), ll = __halves2bfloat162(l0, l1);
        *reinterpret_cast<uint32_t*>(g_Xhi + (size_t)r * 144 + kp * 4) = *reinterpret_cast<uint32_t*>(&hh);
        *reinterpret_cast<uint32_t*>(g_Xlo + (size_t)r * 144 + kp * 4) = *reinterpret_cast<uint32_t*>(&ll);
    } else if (idx < PREP_X + 12288) {
        int i = idx - PREP_X;
        int n = i >> 5, kp = i & 31;               // 384 rows x 32 k-pairs
        int t = n >> 7, c = n & 127, k = kp * 2;
        float w0 = W1[(size_t)(t * 64 + k) * 128 + c];
        float w1 = W1[(size_t)(t * 64 + k + 1) * 128 + c];
        __nv_bfloat16 h0, l0, h1, l1;
        split_bf16(w0, h0, l0);
        split_bf16(w1, h1, l1);
        __nv_bfloat162 hh = __halves2bfloat162(h0, h1), ll = __halves2bfloat162(l0, l1);
        *reinterpret_cast<uint32_t*>(g_W1hi + n * 144 + kp * 4) = *reinterpret_cast<uint32_t*>(&hh);
        *reinterpret_cast<uint32_t*>(g_W1lo + n * 144 + kp * 4) = *reinterpret_cast<uint32_t*>(&ll);
    } else if (idx < PREP_TOTAL) {
        int i = idx - PREP_X - 12288;              // 64 rows x 64 k-pairs
        int n = i >> 6, kp = i & 63, k = kp * 2;
        float w0 = W2[(size_t)k * 64 + n];
        float w1 = W2[(size_t)(k + 1) * 64 + n];
        __nv_bfloat16 h0, l0, h1, l1;
        split_bf16(w0, h0, l0);
        split_bf16(w1, h1, l1);
        __nv_bfloat162 hh = __halves2bfloat162(h0, h1), ll = __halves2bfloat162(l0, l1);
        *reinterpret_cast<uint32_t*>(g_W2hi + n * 272 + kp * 4) = *reinterpret_cast<uint32_t*>(&hh);
        *reinterpret_cast<uint32_t*>(g_W2lo + n * 272 + kp * 4) = *reinterpret_cast<uint32_t*>(&ll);
    }
}

// ---------------------------------------------------------------------------
// Kernel 1: PQR = x @ W1concat.  CTA tile M=64 x N=128, grid (1024, 3 passes).
//   256 threads, 8 warps (2M x 4N), warp tile m32n32, K=64 (4 k-steps).
//   smem: A hi/lo 64x144; B hi/lo 128x144.  55296 B -> 2 CTAs/SM, 16 warps.
// ---------------------------------------------------------------------------
static constexpr int SMEM1_BYTES = 2 * 64 * 144 + 2 * 128 * 144;   // 55296

__global__ __launch_bounds__(256, 2)
void gemm1_kernel(const float* __restrict__ b1) {
    extern __shared__ char sm[];
    const int tid = threadIdx.x, wid = tid >> 5, lane = tid & 31;
    const int gr = lane >> 2, tg = lane & 3;
    const int warpM = wid >> 2, warpN = wid & 3;   // 2 x 4
    const int m0 = blockIdx.x * 64, pass = blockIdx.y;

    char* Ah = sm;                                 //  9216
    char* Al = sm + 9216;                          //  9216
    char* Bh = sm + 18432;                         // 18432
    char* Bl = sm + 36864;                         // 18432

    // A tiles: verbatim copy of x image rows [m0, m0+64)  (576 uint4/plane)
    {
        const uint4* sh = reinterpret_cast<const uint4*>(g_Xhi + (size_t)m0 * 144);
        const uint4* sl = reinterpret_cast<const uint4*>(g_Xlo + (size_t)m0 * 144);
        uint4* dh = reinterpret_cast<uint4*>(Ah);
        uint4* dl = reinterpret_cast<uint4*>(Al);
        for (int i = tid; i < 576; i += 256) { dh[i] = sh[i]; dl[i] = sl[i]; }
    }
    // B tiles: verbatim copy of this pass's 128-row weight slice (1152 uint4)
    {
        const uint4* sh = reinterpret_cast<const uint4*>(g_W1hi + pass * 128 * 144);
        const uint4* sl = reinterpret_cast<const uint4*>(g_W1lo + pass * 128 * 144);
        uint4* dh = reinterpret_cast<uint4*>(Bh);
        uint4* dl = reinterpret_cast<uint4*>(Bl);
        for (int i = tid; i < 1152; i += 256) { dh[i] = sh[i]; dl[i] = sl[i]; }
    }
    __syncthreads();

    float acc[2][4][4];
#pragma unroll
    for (int mt = 0; mt < 2; mt++)
#pragma unroll
        for (int nt = 0; nt < 4; nt++)
#pragma unroll
            for (int e = 0; e < 4; e++) acc[mt][nt][e] = 0.f;

#pragma unroll
    for (int ks = 0; ks < 4; ks++) {
        const int kb = ks * 32 + tg * 4;
        uint32_t ah[2][4], al[2][4], bh[4][2], bl[4][2];
#pragma unroll
        for (int mt = 0; mt < 2; mt++) {
            const char* p = Ah + (warpM * 32 + mt * 16 + gr) * 144 + kb;
            const char* q = Al + (warpM * 32 + mt * 16 + gr) * 144 + kb;
            ah[mt][0] = *reinterpret_cast<const uint32_t*>(p);
            ah[mt][1] = *reinterpret_cast<const uint32_t*>(p + 8 * 144);
            ah[mt][2] = *reinterpret_cast<const uint32_t*>(p + 16);
            ah[mt][3] = *reinterpret_cast<const uint32_t*>(p + 8 * 144 + 16);
            al[mt][0] = *reinterpret_cast<const uint32_t*>(q);
            al[mt][1] = *reinterpret_cast<const uint32_t*>(q + 8 * 144);
            al[mt][2] = *reinterpret_cast<const uint32_t*>(q + 16);
            al[mt][3] = *reinterpret_cast<const uint32_t*>(q + 8 * 144 + 16);
        }
#pragma unroll
        for (int nt = 0; nt < 4; nt++) {
            const char* p = Bh + (warpN * 32 + nt * 8 + gr) * 144 + kb;
            const char* q = Bl + (warpN * 32 + nt * 8 + gr) * 144 + kb;
            bh[nt][0] = *reinterpret_cast<const uint32_t*>(p);
            bh[nt][1] = *reinterpret_cast<const uint32_t*>(p + 16);
            bl[nt][0] = *reinterpret_cast<const uint32_t*>(q);
            bl[nt][1] = *reinterpret_cast<const uint32_t*>(q + 16);
        }
#pragma unroll
        for (int mt = 0; mt < 2; mt++)
#pragma unroll
            for (int nt = 0; nt < 4; nt++) {
                mma16816(acc[mt][nt], ah[mt], bh[nt]);
                mma16816(acc[mt][nt], ah[mt], bl[nt]);
                mma16816(acc[mt][nt], al[mt], bh[nt]);
            }
    }

    // Epilogue: direct float2 stores (+b1 on pass 0)
#pragma unroll
    for (int mt = 0; mt < 2; mt++) {
        int row = m0 + warpM * 32 + mt * 16 + gr;
#pragma unroll
        for (int nt = 0; nt < 4; nt++) {
            int colL = warpN * 32 + nt * 8 + tg * 2;
            float2 v0 = make_float2(acc[mt][nt][0], acc[mt][nt][1]);
            float2 v1 = make_float2(acc[mt][nt][2], acc[mt][nt][3]);
            if (pass == 0) {
                float2 bb = *reinterpret_cast<const float2*>(b1 + colL);
                v0.x += bb.x; v0.y += bb.y; v1.x += bb.x; v1.y += bb.y;
            }
            int col = pass * 128 + colL;
            *reinterpret_cast<float2*>(g_PQR + (size_t)row * 384 + col) = v0;
            *reinterpret_cast<float2*>(g_PQR + (size_t)(row + 8) * 384 + col) = v1;
        }
    }
}

// ---------------------------------------------------------------------------
// Kernel 2: G = mean_s gelu(P + Q[j] + R[k]); emits split-bf16 planes at
//   pitch 272B (gemm2's exact smem layout). One warp per node.
// ---------------------------------------------------------------------------
__device__ __forceinline__ float gelu_f(float v) {
    return 0.5f * v * (1.0f + erff(v * 0.70710678118654752f));
}

__global__ __launch_bounds__(256)
void mid_kernel(const int* __restrict__ jidx, const int* __restrict__ kidx) {
    int gw = (int)((blockIdx.x * 256u + threadIdx.x) >> 5);    // node 0..65535
    int lane = threadIdx.x & 31;
    int base = (gw >> 13) << 13;                               // batch row base
    const float4* P4 = reinterpret_cast<const float4*>(g_PQR); // row stride 96 f4

    float4 p = P4[(size_t)gw * 96 + lane];
    float ax = 0.f, ay = 0.f, az = 0.f, aw = 0.f;

#pragma unroll
    for (int half = 0; half < 2; half++) {
        int s0 = half * 4;
        int j[4], k[4];
#pragma unroll
        for (int u = 0; u < 4; u++) {
            j[u] = __ldg(jidx + gw * 8 + s0 + u);
            k[u] = __ldg(kidx + gw * 8 + s0 + u);
        }
        float4 q[4], r[4];
#pragma unroll
        for (int u = 0; u < 4; u++) {
            q[u] = P4[(size_t)(base + j[u]) * 96 + 32 + lane];
            r[u] = P4[(size_t)(base + k[u]) * 96 + 64 + lane];
        }
#pragma unroll
        for (int u = 0; u < 4; u++) {
            ax += gelu_f(p.x + q[u].x + r[u].x);
            ay += gelu_f(p.y + q[u].y + r[u].y);
            az += gelu_f(p.z + q[u].z + r[u].z);
            aw += gelu_f(p.w + q[u].w + r[u].w);
        }
    }
    float g0 = ax * 0.125f, g1 = ay * 0.125f, g2 = az * 0.125f, g3 = aw * 0.125f;
    __nv_bfloat16 h0, l0, h1, l1, h2, l2, h3, l3;
    split_bf16(g0, h0, l0);
    split_bf16(g1, h1, l1);
    split_bf16(g2, h2, l2);
    split_bf16(g3, h3, l3);
    __nv_bfloat162 hA = __halves2bfloat162(h0, h1), hB = __halves2bfloat162(h2, h3);
    __nv_bfloat162 lA = __halves2bfloat162(l0, l1), lB = __halves2bfloat162(l2, l3);
    uint2 hv = make_uint2(*reinterpret_cast<uint32_t*>(&hA), *reinterpret_cast<uint32_t*>(&hB));
    uint2 lv = make_uint2(*reinterpret_cast<uint32_t*>(&lA), *reinterpret_cast<uint32_t*>(&lB));
    *reinterpret_cast<uint2*>(g_Ghi + (size_t)gw * 272 + lane * 8) = hv;
    *reinterpret_cast<uint2*>(g_Glo + (size_t)gw * 272 + lane * 8) = lv;
}

// ---------------------------------------------------------------------------
// Kernel 3: out = G @ W2 + b2.  CTA tile M=64 x N=64, grid 1024.
//   128 threads, 4 warps (2M x 2N), warp tile m32n32, K=128 (8 k-steps).
//   smem: A hi/lo 64x272; B hi/lo 64x272.  69632 B -> 3 CTAs/SM, 12 warps.
// ---------------------------------------------------------------------------
static constexpr int SMEM2_BYTES = 4 * 64 * 272;   // 69632

__global__ __launch_bounds__(128, 3)
void gemm2_kernel(const float* __restrict__ b2, float* __restrict__ out) {
    extern __shared__ char sm[];
    const int tid = threadIdx.x, wid = tid >> 5, lane = tid & 31;
    const int gr = lane >> 2, tg = lane & 3;
    const int warpM = wid >> 1, warpN = wid & 1;   // 2 x 2
    const int m0 = blockIdx.x * 64;

    char* Ah = sm;                                 // 17408
    char* Al = sm + 17408;
    char* Bh = sm + 34816;
    char* Bl = sm + 52224;

    // A tiles: verbatim copy of G image rows [m0, m0+64)  (1088 uint4/plane)
    {
        const uint4* sh = reinterpret_cast<const uint4*>(g_Ghi + (size_t)m0 * 272);
        const uint4* sl = reinterpret_cast<const uint4*>(g_Glo + (size_t)m0 * 272);
        uint4* dh = reinterpret_cast<uint4*>(Ah);
        uint4* dl = reinterpret_cast<uint4*>(Al);
        for (int i = tid; i < 1088; i += 128) { dh[i] = sh[i]; dl[i] = sl[i]; }
    }
    // B tiles: verbatim copy of W2 images (1088 uint4/plane)
    {
        const uint4* sh = reinterpret_cast<const uint4*>(g_W2hi);
        const uint4* sl = reinterpret_cast<const uint4*>(g_W2lo);
        uint4* dh = reinterpret_cast<uint4*>(Bh);
        uint4* dl = reinterpret_cast<uint4*>(Bl);
        for (int i = tid; i < 1088; i += 128) { dh[i] = sh[i]; dl[i] = sl[i]; }
    }
    __syncthreads();

    float acc[2][4][4];
#pragma unroll
    for (int mt = 0; mt < 2; mt++)
#pragma unroll
        for (int nt = 0; nt < 4; nt++)
#pragma unroll
            for (int e = 0; e < 4; e++) acc[mt][nt][e] = 0.f;

#pragma unroll
    for (int ks = 0; ks < 8; ks++) {
        const int kb = ks * 32 + tg * 4;
        uint32_t ah[2][4], al[2][4], bh[4][2], bl[4][2];
#pragma unroll
        for (int mt = 0; mt < 2; mt++) {
            const char* p = Ah + (warpM * 32 + mt * 16 + gr) * 272 + kb;
            const char* q = Al + (warpM * 32 + mt * 16 + gr) * 272 + kb;
            ah[mt][0] = *reinterpret_cast<const uint32_t*>(p);
            ah[mt][1] = *reinterpret_cast<const uint32_t*>(p + 8 * 272);
            ah[mt][2] = *reinterpret_cast<const uint32_t*>(p + 16);
            ah[mt][3] = *reinterpret_cast<const uint32_t*>(p + 8 * 272 + 16);
            al[mt][0] = *reinterpret_cast<const uint32_t*>(q);
            al[mt][1] = *reinterpret_cast<const uint32_t*>(q + 8 * 272);
            al[mt][2] = *reinterpret_cast<const uint32_t*>(q + 16);
            al[mt][3] = *reinterpret_cast<const uint32_t*>(q + 8 * 272 + 16);
        }
#pragma unroll
        for (int nt = 0; nt < 4; nt++) {
            const char* p = Bh + (warpN * 32 + nt * 8 + gr) * 272 + kb;
            const char* q = Bl + (warpN * 32 + nt * 8 + gr) * 272 + kb;
            bh[nt][0] = *reinterpret_cast<const uint32_t*>(p);
            bh[nt][1] = *reinterpret_cast<const uint32_t*>(p + 16);
            bl[nt][0] = *reinterpret_cast<const uint32_t*>(q);
            bl[nt][1] = *reinterpret_cast<const uint32_t*>(q + 16);
        }
#pragma unroll
        for (int mt = 0; mt < 2; mt++)
#pragma unroll
            for (int nt = 0; nt < 4; nt++) {
                mma16816(acc[mt][nt], ah[mt], bh[nt]);
                mma16816(acc[mt][nt], ah[mt], bl[nt]);
                mma16816(acc[mt][nt], al[mt], bh[nt]);
            }
    }

    // Epilogue: +b2, direct float2 stores
#pragma unroll
    for (int mt = 0; mt < 2; mt++) {
        int row = m0 + warpM * 32 + mt * 16 + gr;
#pragma unroll
        for (int nt = 0; nt < 4; nt++) {
            int col = warpN * 32 + nt * 8 + tg * 2;
            float2 bb = *reinterpret_cast<const float2*>(b2 + col);
            float2 v0 = make_float2(acc[mt][nt][0] + bb.x, acc[mt][nt][1] + bb.y);
            float2 v1 = make_float2(acc[mt][nt][2] + bb.x, acc[mt][nt][3] + bb.y);
            *reinterpret_cast<float2*>(out + (size_t)row * 64 + col) = v0;
            *reinterpret_cast<float2*>(out + (size_t)(row + 8) * 64 + col) = v1;
        }
    }
}

// ---------------------------------------------------------------------------
// Host launcher (graph-capturable: kernel launches only)
// ---------------------------------------------------------------------------
extern "C" void kernel_launch(void* const* d_in, const int* in_sizes, int n_in,
                              void* d_out, int out_size) {
    (void)in_sizes; (void)n_in; (void)out_size;
    const float* x   = (const float*)d_in[0];
    const int*   jid = (const int*)  d_in[1];
    const int*   kid = (const int*)  d_in[2];
    const float* W1  = (const float*)d_in[3];
    const float* b1  = (const float*)d_in[4];
    const float* W2  = (const float*)d_in[5];
    const float* b2  = (const float*)d_in[6];
    float* out = (float*)d_out;

    cudaFuncSetAttribute(gemm1_kernel, cudaFuncAttributeMaxDynamicSharedMemorySize, SMEM1_BYTES);
    cudaFuncSetAttribute(gemm2_kernel, cudaFuncAttributeMaxDynamicSharedMemorySize, SMEM2_BYTES);

    prep_kernel<<<(PREP_TOTAL + 255) / 256, 256>>>(x, W1, W2);
    gemm1_kernel<<<dim3(1024, 3), 256, SMEM1_BYTES>>>(b1);
    mid_kernel<<<NODES / 8, 256>>>(jid, kid);
    gemm2_kernel<<<1024, 128, SMEM2_BYTES>>>(b2, out);
}